// round 13
// baseline (speedup 1.0000x reference)
#include <cuda_runtime.h>
#include <cuda_bf16.h>
#include <cstdint>
#include <cstddef>

#define N_STEPS 4096
#define NU 8
#define R 256
#define NX 64
#define NY 8
#define L 16
#define C_CHUNKS (N_STEPS / L)   // 256
#define QTOT (NU * L)            // 128
#define KDIM 192
#define MW 1152

typedef unsigned long long ull;

// ---------------- device scratch ----------------
__device__ float g_KcatT[QTOT * NX];
__device__ float g_AL[NX * NX];
__device__ float g_buf[(size_t)C_CHUNKS * NX * R];           // Pfin -> Xstart
__device__ float g_Apow[16 * NX * NX];
__device__ __align__(16) __nv_bfloat16 g_Whi[9 * 3 * 8192];  // [mt][kb][128][64]
__device__ __align__(16) __nv_bfloat16 g_Wlo[9 * 3 * 8192];
__device__ __align__(16) __nv_bfloat16 g_Bhi[(size_t)C_CHUNKS * 3 * 16384]; // [c][kb][256][64]
__device__ __align__(16) __nv_bfloat16 g_Blo[(size_t)C_CHUNKS * 3 * 16384];

// ---------------- helpers ----------------
__device__ __forceinline__ ull pack2(float lo, float hi) {
    ull v; asm("mov.b64 %0,{%1,%2};" : "=l"(v) : "f"(lo), "f"(hi)); return v;
}
__device__ __forceinline__ void unpack2(ull v, float& lo, float& hi) {
    asm("mov.b64 {%0,%1},%2;" : "=f"(lo), "=f"(hi) : "l"(v));
}
__device__ __forceinline__ void fma2ip(ull& d, ull a, ull b) {
    asm("fma.rn.f32x2 %0,%1,%2,%0;" : "+l"(d) : "l"(a), "l"(b));
}
__device__ __forceinline__ uint32_t smem_u32(const void* p) {
    uint32_t a;
    asm("{ .reg .u64 t; cvta.to.shared.u64 t, %1; cvt.u32.u64 %0, t; }" : "=r"(a) : "l"(p));
    return a;
}
__device__ __forceinline__ void bfsplit(float v, __nv_bfloat16& h, __nv_bfloat16& l) {
    h = __float2bfloat16(v);
    l = __float2bfloat16(v - __bfloat162float(h));
}
// ldmatrix x4 (four 8x8 b16 tiles)
__device__ __forceinline__ void ldm4(uint32_t* r, uint32_t addr) {
    asm volatile("ldmatrix.sync.aligned.m8n8.x4.shared.b16 {%0,%1,%2,%3}, [%4];"
        : "=r"(r[0]), "=r"(r[1]), "=r"(r[2]), "=r"(r[3]) : "r"(addr));
}
// mma m16n8k16 bf16, f32 accum
__device__ __forceinline__ void mma16816(float* d, const uint32_t* a, uint32_t b0, uint32_t b1) {
    asm volatile("mma.sync.aligned.m16n8k16.row.col.f32.bf16.bf16.f32 "
        "{%0,%1,%2,%3}, {%4,%5,%6,%7}, {%8,%9}, {%0,%1,%2,%3};"
        : "+f"(d[0]), "+f"(d[1]), "+f"(d[2]), "+f"(d[3])
        : "r"(a[0]), "r"(a[1]), "r"(a[2]), "r"(a[3]), "r"(b0), "r"(b1));
}

// ---------------------------------------------------------------------------
// Kernel 0 (R9, proven): K[s]=A^s B by doubling + A^16 in smem. 512 threads.
// ---------------------------------------------------------------------------
extern __shared__ float psm[];
__global__ void k_precompute(const float* __restrict__ A, const float* __restrict__ B) {
    float* sP = psm;
    float* sQ = psm + 4096;
    float* sW = psm + 8192;
    const int t = threadIdx.x;
    const int i = t >> 3;
    const int g = t & 7;

    for (int idx = t; idx < NX * NX; idx += 512) sP[idx] = A[idx];
    for (int idx = t; idx < NX * NU; idx += 512)
        sW[(idx / NU) * QTOT + (idx % NU)] = B[idx];
    __syncthreads();

    float* p = sP;
    float* q = sQ;
    int w = NU;
    for (int m = 0; m < 4; m++) {
        const int cw = w >> 3;
        if (cw == 1) {
            float s0 = 0.f, s1 = 0.f, s2 = 0.f, s3 = 0.f;
            #pragma unroll 4
            for (int k = 0; k < NX; k += 4) {
                s0 += p[i * NX + k + 0] * sW[(k + 0) * QTOT + g];
                s1 += p[i * NX + k + 1] * sW[(k + 1) * QTOT + g];
                s2 += p[i * NX + k + 2] * sW[(k + 2) * QTOT + g];
                s3 += p[i * NX + k + 3] * sW[(k + 3) * QTOT + g];
            }
            sW[i * QTOT + w + g] = (s0 + s1) + (s2 + s3);
        } else {
            const int jc0 = g * cw;
            const int nv = cw >> 1;
            ull acc[4] = {0ull, 0ull, 0ull, 0ull};
            for (int k = 0; k < NX; k++) {
                float a = p[i * NX + k];
                ull pk = pack2(a, a);
                const ull* wr = (const ull*)(sW + k * QTOT + jc0);
                #pragma unroll
                for (int v = 0; v < 4; v++)
                    if (v < nv) fma2ip(acc[v], pk, wr[v]);
            }
            ull* out = (ull*)(sW + i * QTOT + w + jc0);
            #pragma unroll
            for (int v = 0; v < 4; v++)
                if (v < nv) out[v] = acc[v];
        }
        {
            const int jb = g * 8;
            ull acc[4] = {0ull, 0ull, 0ull, 0ull};
            for (int k = 0; k < NX; k++) {
                float a = p[i * NX + k];
                ull pk = pack2(a, a);
                const ulonglong2* pr = (const ulonglong2*)(p + k * NX + jb);
                ulonglong2 w0 = pr[0], w1 = pr[1];
                fma2ip(acc[0], pk, w0.x);
                fma2ip(acc[1], pk, w0.y);
                fma2ip(acc[2], pk, w1.x);
                fma2ip(acc[3], pk, w1.y);
            }
            ull* out = (ull*)(q + i * NX + jb);
            out[0] = acc[0]; out[1] = acc[1]; out[2] = acc[2]; out[3] = acc[3];
        }
        __syncthreads();
        float* tmp = p; p = q; q = tmp;
        w <<= 1;
    }
    for (int idx = t; idx < NX * NX; idx += 512) g_AL[idx] = p[idx];
    for (int idx = t; idx < NX * QTOT; idx += 512) {
        int ii = idx >> 7, col = idx & 127;
        int s = col >> 3, j = col & 7;
        g_KcatT[(((L - 1 - s) * NU + j) * NX) + ii] = sW[ii * QTOT + col];
    }
}

// ---------------------------------------------------------------------------
// Kernel 1 (R9): Pfin -> g_buf.
// ---------------------------------------------------------------------------
__global__ void k_phase1(const float* __restrict__ u) {
    __shared__ __align__(16) float sU[64 * 64];
    __shared__ __align__(16) float sKT[64 * 64];
    const int c = blockIdx.x;
    const int r0 = blockIdx.y * 64;
    const int t = threadIdx.x;
    const int r = t & 63;
    const int ig = t >> 6;

    ull acc2[8];
    #pragma unroll
    for (int m = 0; m < 8; m++) acc2[m] = 0ull;
    const float* Uc = u + (size_t)c * L * NU * R;

    for (int qb = 0; qb < QTOT / 64; qb++) {
        __syncthreads();
        #pragma unroll
        for (int m = 0; m < 16; m++) {
            int qq = m * 4 + ig;
            sU[qq * 64 + r] = Uc[(size_t)(qb * 64 + qq) * R + r0 + r];
        }
        for (int idx = t; idx < 4096; idx += 256)
            sKT[idx] = g_KcatT[qb * 64 * 64 + idx];
        __syncthreads();
        #pragma unroll 8
        for (int qq = 0; qq < 64; qq++) {
            float uval = sU[qq * 64 + r];
            ull uv = pack2(uval, uval);
            const ulonglong2* k2p = (const ulonglong2*)(sKT + qq * 64 + ig * 16);
            #pragma unroll
            for (int m2 = 0; m2 < 4; m2++) {
                ulonglong2 kk = k2p[m2];
                fma2ip(acc2[2 * m2 + 0], kk.x, uv);
                fma2ip(acc2[2 * m2 + 1], kk.y, uv);
            }
        }
    }
    #pragma unroll
    for (int m = 0; m < 8; m++) {
        float lo, hi; unpack2(acc2[m], lo, hi);
        int i = ig * 16 + 2 * m;
        g_buf[((size_t)c * NX + i) * R + r0 + r]     = lo;
        g_buf[((size_t)c * NX + i + 1) * R + r0 + r] = hi;
    }
}

// ---------------------------------------------------------------------------
// Kernel 2 (R9): boundary scan, 4-deep prefetch. g_buf: Pfin -> Xstart.
// ---------------------------------------------------------------------------
__global__ void k_phase2(const float* __restrict__ x0) {
    __shared__ __align__(16) float sxf[2][2][NX];
    const int t = threadIdx.x;
    const int r = t & 1;
    const int i = t >> 1;
    const int rg = blockIdx.x * 2 + r;

    ull a2[32];
    const ull* arow = (const ull*)(g_AL + i * NX);
    #pragma unroll
    for (int j2 = 0; j2 < 32; j2++) a2[j2] = arow[j2];

    float xi = x0[i * R + rg];
    sxf[0][r][i] = xi;
    __syncthreads();

    float pfq[4];
    #pragma unroll
    for (int d = 0; d < 4; d++)
        pfq[d] = g_buf[((size_t)d * NX + i) * R + rg];

    int p = 0;
    for (int c = 0; c < C_CHUNKS; c++) {
        float pf = pfq[c & 3];
        float pfut = (c + 4 < C_CHUNKS) ? g_buf[((size_t)(c + 4) * NX + i) * R + rg] : 0.f;
        g_buf[((size_t)c * NX + i) * R + rg] = xi;

        const ull* xsrc = (const ull*)&sxf[p][r][0];
        ull A0 = 0ull, A1 = 0ull, A2 = 0ull, A3 = 0ull;
        #pragma unroll
        for (int j2 = 0; j2 < 32; j2 += 4) {
            fma2ip(A0, a2[j2 + 0], xsrc[j2 + 0]);
            fma2ip(A1, a2[j2 + 1], xsrc[j2 + 1]);
            fma2ip(A2, a2[j2 + 2], xsrc[j2 + 2]);
            fma2ip(A3, a2[j2 + 3], xsrc[j2 + 3]);
        }
        float s0, s1, s2, s3, s4, s5, s6, s7;
        unpack2(A0, s0, s1); unpack2(A1, s2, s3);
        unpack2(A2, s4, s5); unpack2(A3, s6, s7);
        xi = (((s0 + s1) + (s2 + s3)) + ((s4 + s5) + (s6 + s7))) + pf;

        pfq[c & 3] = pfut;
        sxf[p ^ 1][r][i] = xi;
        __syncthreads();
        p ^= 1;
    }
}

// ---------------------------------------------------------------------------
// Kernel W: build W (1152 x 192) -> bf16 hi/lo blocks [mt][kb][128][64].
// 1 CTA, 512 threads.
// ---------------------------------------------------------------------------
extern __shared__ float wsm[];
__global__ void k_wbuild(const float* __restrict__ A, const float* __restrict__ Cy,
                         const float* __restrict__ Dg) {
    float* sA  = wsm;            // 4096
    float* sP  = wsm + 4096;     // 4096
    float* sQ  = wsm + 8192;     // 4096
    float* sCP = wsm + 12288;    // 16*512
    float* sCK = wsm + 20480;    // 16*64
    const int t = threadIdx.x;   // 512

    for (int idx = t; idx < 4096; idx += 512) {
        sA[idx] = A[idx];
        sP[idx] = ((idx >> 6) == (idx & 63)) ? 1.f : 0.f;
    }
    __syncthreads();

    float* p = sP;
    float* q = sQ;
    for (int k = 0; k < 16; k++) {
        for (int idx = t; idx < 4096; idx += 512) g_Apow[k * 4096 + idx] = p[idx];
        {   // CP[k] = C @ p
            int o = t >> 6, m = t & 63;
            float a = 0.f;
            for (int mm = 0; mm < 64; mm++) a += Cy[o * 64 + mm] * p[mm * 64 + m];
            sCP[k * 512 + t] = a;
        }
        __syncthreads();
        if (k < 15) {
            for (int idx = t; idx < 4096; idx += 512) {
                int i = idx >> 6, j = idx & 63;
                float a0 = 0.f, a1 = 0.f, a2 = 0.f, a3 = 0.f;
                #pragma unroll 4
                for (int m = 0; m < 64; m += 4) {
                    a0 += sA[i * 64 + m + 0] * p[(m + 0) * 64 + j];
                    a1 += sA[i * 64 + m + 1] * p[(m + 1) * 64 + j];
                    a2 += sA[i * 64 + m + 2] * p[(m + 2) * 64 + j];
                    a3 += sA[i * 64 + m + 3] * p[(m + 3) * 64 + j];
                }
                q[idx] = (a0 + a1) + (a2 + a3);
            }
            __syncthreads();
            float* tmp = p; p = q; q = tmp;
        }
    }
    // CK[s] = C A^s B
    for (int idx = t; idx < 1024; idx += 512) {
        int s = idx >> 6, oj = idx & 63, o = oj >> 3, j = oj & 7;
        const float* kc = g_KcatT + ((size_t)(15 - s) * 8 + j) * 64;
        float a = 0.f;
        for (int i = 0; i < 64; i++) a += Cy[o * 64 + i] * kc[i];
        sCK[idx] = a;
    }
    __syncthreads();

    for (int idx = t; idx < MW * KDIM; idx += 512) {
        int grow = idx / KDIM, col = idx % KDIM;
        float v;
        if (grow < 1024) {
            int step = grow >> 6, i = grow & 63;
            if (col < 64) v = g_Apow[step * 4096 + i * 64 + col];
            else {
                int qc = col - 64, tt = qc >> 3, j = qc & 7;
                v = (tt < step) ? g_KcatT[(((size_t)(16 - step + tt) * 8 + j) * 64) + i] : 0.f;
            }
        } else {
            int row = grow - 1024, step = row >> 3, o = row & 7;
            if (col < 64) v = sCP[step * 512 + o * 64 + col];
            else {
                int qc = col - 64, tt = qc >> 3, j = qc & 7;
                if (tt < step)       v = sCK[(step - 1 - tt) * 64 + o * 8 + j];
                else if (tt == step) v = Dg[o * 8 + j];
                else                 v = 0.f;
            }
        }
        __nv_bfloat16 h, l; bfsplit(v, h, l);
        int mt = grow >> 7, row = grow & 127, kb = col >> 6, ck = col & 63;
        size_t e = ((size_t)(mt * 3 + kb)) * 8192 + row * 64 + ck;
        g_Whi[e] = h;
        g_Wlo[e] = l;
    }
}

// ---------------------------------------------------------------------------
// Kernel Bprep: per chunk, Rhs^T (256 x 192) -> bf16 hi/lo [c][kb][256][64].
// 256 CTAs x 256 thr.
// ---------------------------------------------------------------------------
extern __shared__ float bsm[];
__global__ void k_bprep(const float* __restrict__ u) {
    const int c = blockIdx.x;
    const int t = threadIdx.x;  // 256
    for (int kb = 0; kb < 3; kb++) {
        __syncthreads();
        for (int idx = t; idx < 64 * 256; idx += 256) {
            int k = idx >> 8, r = idx & 255;
            int kg = kb * 64 + k;
            float v;
            if (kg < 64) v = g_buf[((size_t)c * 64 + kg) * 256 + r];
            else {
                int qc = kg - 64;
                v = u[(((size_t)c * 16 + (qc >> 3)) * 8 + (qc & 7)) * 256 + r];
            }
            bsm[r * 65 + k] = v;
        }
        __syncthreads();
        for (int idx = t; idx < 2048; idx += 256) {
            int r = idx >> 3, cc = idx & 7;
            __nv_bfloat16 h8[8], l8[8];
            #pragma unroll
            for (int j = 0; j < 8; j++) {
                float v = bsm[r * 65 + cc * 8 + j];
                bfsplit(v, h8[j], l8[j]);
            }
            size_t e = ((size_t)(c * 3 + kb)) * 16384 + r * 64 + cc * 8;
            *(uint4*)(g_Bhi + e) = *(uint4*)h8;
            *(uint4*)(g_Blo + e) = *(uint4*)l8;
        }
    }
}

// ---------------------------------------------------------------------------
// Kernel GEMM (mma.sync): Out[mt,c](128x256) = W[mt](128x192) @ Rhs[c](192x256),
// bf16 3-product hi/lo. Grid (256, 9), 512 threads (16 warps, 4x4 grid,
// warp tile 32x64). smem rows padded to 72 bf16 (144B) -> conflict-free ldmatrix.
// ---------------------------------------------------------------------------
extern __shared__ __align__(16) char gsm[];
#define SW_H 0
#define SW_L 18432
#define SB_H 36864
#define SB_L 73728
#define SMEM_G 110592

__global__ void __launch_bounds__(512) k_gemm(float* __restrict__ outY,
                                              float* __restrict__ outX) {
    const int c = blockIdx.x, mt = blockIdx.y;
    const int t = threadIdx.x;
    const int warp = t >> 5, lane = t & 31;
    const int wm = warp & 3, wn = warp >> 2;       // warp tile: rows wm*32, cols wn*64
    const uint32_t sbase = smem_u32(gsm);

    float acc[2][8][4];
    #pragma unroll
    for (int a = 0; a < 2; a++)
        #pragma unroll
        for (int b = 0; b < 8; b++)
            #pragma unroll
            for (int d = 0; d < 4; d++) acc[a][b][d] = 0.f;

    // ldmatrix source addresses (byte offsets within padded tiles)
    const int alr = lane & 15, alc = (lane >> 4) * 8;          // A: row, col-bf16
    const int bln = (lane & 7) + ((lane >> 4) << 3);           // B: n within 16-group
    const int blk = ((lane >> 3) & 1) * 8;                     // B: k offset

    #pragma unroll 1
    for (int kb = 0; kb < 3; kb++) {
        // ---- stage 4 blocks into padded smem ----
        {
            const uint4* swh = (const uint4*)(g_Whi + (size_t)(mt * 3 + kb) * 8192);
            const uint4* swl = (const uint4*)(g_Wlo + (size_t)(mt * 3 + kb) * 8192);
            for (int i = t; i < 1024; i += 512) {
                int row = i >> 3, ch = i & 7;
                *(uint4*)(gsm + SW_H + row * 144 + ch * 16) = swh[i];
                *(uint4*)(gsm + SW_L + row * 144 + ch * 16) = swl[i];
            }
            const uint4* sbh = (const uint4*)(g_Bhi + (size_t)(c * 3 + kb) * 16384);
            const uint4* sbl = (const uint4*)(g_Blo + (size_t)(c * 3 + kb) * 16384);
            for (int i = t; i < 2048; i += 512) {
                int row = i >> 3, ch = i & 7;
                *(uint4*)(gsm + SB_H + row * 144 + ch * 16) = sbh[i];
                *(uint4*)(gsm + SB_L + row * 144 + ch * 16) = sbl[i];
            }
        }
        __syncthreads();

        #pragma unroll
        for (int pass = 0; pass < 3; pass++) {
            const uint32_t wb = sbase + (pass == 1 ? SW_L : SW_H);
            const uint32_t bb = sbase + (pass == 2 ? SB_L : SB_H);
            #pragma unroll
            for (int ks = 0; ks < 4; ks++) {
                uint32_t afr[2][4];
                #pragma unroll
                for (int m2 = 0; m2 < 2; m2++) {
                    int row = wm * 32 + m2 * 16 + alr;
                    ldm4(afr[m2], wb + row * 144 + (ks * 16 + alc) * 2);
                }
                #pragma unroll
                for (int pp = 0; pp < 4; pp++) {
                    uint32_t bfr[4];
                    int n = wn * 64 + pp * 16 + bln;
                    ldm4(bfr, bb + n * 144 + (ks * 16 + blk) * 2);
                    mma16816(acc[0][2 * pp + 0], afr[0], bfr[0], bfr[1]);
                    mma16816(acc[0][2 * pp + 1], afr[0], bfr[2], bfr[3]);
                    mma16816(acc[1][2 * pp + 0], afr[1], bfr[0], bfr[1]);
                    mma16816(acc[1][2 * pp + 1], afr[1], bfr[2], bfr[3]);
                }
            }
        }
        __syncthreads();
    }

    // ---- epilogue: write f32 results ----
    const int g = lane >> 2, tq = lane & 3;
    #pragma unroll
    for (int m2 = 0; m2 < 2; m2++) {
        #pragma unroll
        for (int half = 0; half < 2; half++) {
            int grow = mt * 128 + wm * 32 + m2 * 16 + g + half * 8;
            float* dst;
            if (grow < 1024) {
                int step = grow >> 6, i = grow & 63;
                dst = outX + (((size_t)c * 16 + step) * 64 + i) * 256;
            } else {
                int yr = grow - 1024;
                int step = yr >> 3, o = yr & 7;
                dst = outY + (((size_t)c * 16 + step) * 8 + o) * 256;
            }
            #pragma unroll
            for (int nt = 0; nt < 8; nt++) {
                int n = wn * 64 + nt * 8 + 2 * tq;
                float2 v = half ? make_float2(acc[m2][nt][2], acc[m2][nt][3])
                                : make_float2(acc[m2][nt][0], acc[m2][nt][1]);
                *(float2*)(dst + n) = v;
            }
        }
    }
}

#define SMEM_P0 ((4096 + 4096 + 8192) * 4)
#define SMEM_W  (21504 * 4)
#define SMEM_B  (256 * 65 * 4)

// ---------------------------------------------------------------------------
extern "C" void kernel_launch(void* const* d_in, const int* in_sizes, int n_in,
                              void* d_out, int out_size) {
    const float* u  = (const float*)d_in[0];
    const float* x0 = (const float*)d_in[1];
    const float* A  = (const float*)d_in[2];
    const float* B  = (const float*)d_in[3];
    const float* Cy = (const float*)d_in[4];
    const float* D  = (const float*)d_in[5];
    float* outY = (float*)d_out;
    float* outX = (float*)d_out + (size_t)N_STEPS * NY * R;

    cudaFuncSetAttribute(k_precompute, cudaFuncAttributeMaxDynamicSharedMemorySize, SMEM_P0);
    cudaFuncSetAttribute(k_wbuild, cudaFuncAttributeMaxDynamicSharedMemorySize, SMEM_W);
    cudaFuncSetAttribute(k_bprep, cudaFuncAttributeMaxDynamicSharedMemorySize, SMEM_B);
    cudaFuncSetAttribute(k_gemm, cudaFuncAttributeMaxDynamicSharedMemorySize, SMEM_G);

    k_precompute<<<1, 512, SMEM_P0>>>(A, B);
    k_wbuild<<<1, 512, SMEM_W>>>(A, Cy, D);
    k_phase1<<<dim3(C_CHUNKS, R / 64), 256>>>(u);
    k_phase2<<<R / 2, 128>>>(x0);
    k_bprep<<<C_CHUNKS, 256, SMEM_B>>>(u);
    k_gemm<<<dim3(C_CHUNKS, 9), 512, SMEM_G>>>(outY, outX);
}

// round 14
// speedup vs baseline: 1.8182x; 1.8182x over previous
#include <cuda_runtime.h>
#include <cstddef>

#define N_STEPS 4096
#define NU 8
#define R 256
#define NX 64
#define NY 8
#define L 16
#define C_CHUNKS (N_STEPS / L)   // 256
#define QTOT (NU * L)            // 128

typedef unsigned long long ull;

// Scratch (device globals)
__device__ float g_KcatT[QTOT * NX];
__device__ float g_AL[NX * NX];
__device__ float g_buf[(size_t)C_CHUNKS * NX * R];  // Pfin -> Xstart

// ---------------- packed f32x2 helpers ----------------
__device__ __forceinline__ ull pack2(float lo, float hi) {
    ull v; asm("mov.b64 %0,{%1,%2};" : "=l"(v) : "f"(lo), "f"(hi)); return v;
}
__device__ __forceinline__ void unpack2(ull v, float& lo, float& hi) {
    asm("mov.b64 {%0,%1},%2;" : "=f"(lo), "=f"(hi) : "l"(v));
}
__device__ __forceinline__ void fma2ip(ull& d, ull a, ull b) {
    asm("fma.rn.f32x2 %0,%1,%2,%0;" : "+l"(d) : "l"(a), "l"(b));
}

// ---------------------------------------------------------------------------
// Kernel 0 (R9): K[s]=A^s B by doubling + A^16, all in smem. 512 threads.
// ---------------------------------------------------------------------------
extern __shared__ float psm[];
__global__ void k_precompute(const float* __restrict__ A, const float* __restrict__ B) {
    float* sP = psm;
    float* sQ = psm + 4096;
    float* sW = psm + 8192;
    const int t = threadIdx.x;
    const int i = t >> 3;
    const int g = t & 7;

    for (int idx = t; idx < NX * NX; idx += 512) sP[idx] = A[idx];
    for (int idx = t; idx < NX * NU; idx += 512)
        sW[(idx / NU) * QTOT + (idx % NU)] = B[idx];
    __syncthreads();

    float* p = sP;
    float* q = sQ;
    int w = NU;
    for (int m = 0; m < 4; m++) {
        const int cw = w >> 3;
        if (cw == 1) {
            float s0 = 0.f, s1 = 0.f, s2 = 0.f, s3 = 0.f;
            #pragma unroll 4
            for (int k = 0; k < NX; k += 4) {
                s0 += p[i * NX + k + 0] * sW[(k + 0) * QTOT + g];
                s1 += p[i * NX + k + 1] * sW[(k + 1) * QTOT + g];
                s2 += p[i * NX + k + 2] * sW[(k + 2) * QTOT + g];
                s3 += p[i * NX + k + 3] * sW[(k + 3) * QTOT + g];
            }
            sW[i * QTOT + w + g] = (s0 + s1) + (s2 + s3);
        } else {
            const int jc0 = g * cw;
            const int nv = cw >> 1;
            ull acc[4] = {0ull, 0ull, 0ull, 0ull};
            for (int k = 0; k < NX; k++) {
                float a = p[i * NX + k];
                ull pk = pack2(a, a);
                const ull* wr = (const ull*)(sW + k * QTOT + jc0);
                #pragma unroll
                for (int v = 0; v < 4; v++)
                    if (v < nv) fma2ip(acc[v], pk, wr[v]);
            }
            ull* out = (ull*)(sW + i * QTOT + w + jc0);
            #pragma unroll
            for (int v = 0; v < 4; v++)
                if (v < nv) out[v] = acc[v];
        }
        {
            const int jb = g * 8;
            ull acc[4] = {0ull, 0ull, 0ull, 0ull};
            for (int k = 0; k < NX; k++) {
                float a = p[i * NX + k];
                ull pk = pack2(a, a);
                const ulonglong2* pr = (const ulonglong2*)(p + k * NX + jb);
                ulonglong2 w0 = pr[0], w1 = pr[1];
                fma2ip(acc[0], pk, w0.x);
                fma2ip(acc[1], pk, w0.y);
                fma2ip(acc[2], pk, w1.x);
                fma2ip(acc[3], pk, w1.y);
            }
            ull* out = (ull*)(q + i * NX + jb);
            out[0] = acc[0]; out[1] = acc[1]; out[2] = acc[2]; out[3] = acc[3];
        }
        __syncthreads();
        float* tmp = p; p = q; q = tmp;
        w <<= 1;
    }
    for (int idx = t; idx < NX * NX; idx += 512) g_AL[idx] = p[idx];
    for (int idx = t; idx < NX * QTOT; idx += 512) {
        int ii = idx >> 7, col = idx & 127;
        int s = col >> 3, j = col & 7;
        g_KcatT[(((L - 1 - s) * NU + j) * NX) + ii] = sW[ii * QTOT + col];
    }
}

// ---------------------------------------------------------------------------
// Kernel 1 (R9): Pfin -> g_buf.
// ---------------------------------------------------------------------------
__global__ void k_phase1(const float* __restrict__ u) {
    __shared__ __align__(16) float sU[64 * 64];
    __shared__ __align__(16) float sKT[64 * 64];
    const int c = blockIdx.x;
    const int r0 = blockIdx.y * 64;
    const int t = threadIdx.x;
    const int r = t & 63;
    const int ig = t >> 6;

    ull acc2[8];
    #pragma unroll
    for (int m = 0; m < 8; m++) acc2[m] = 0ull;
    const float* Uc = u + (size_t)c * L * NU * R;

    for (int qb = 0; qb < QTOT / 64; qb++) {
        __syncthreads();
        #pragma unroll
        for (int m = 0; m < 16; m++) {
            int qq = m * 4 + ig;
            sU[qq * 64 + r] = Uc[(size_t)(qb * 64 + qq) * R + r0 + r];
        }
        for (int idx = t; idx < 4096; idx += 256)
            sKT[idx] = g_KcatT[qb * 64 * 64 + idx];
        __syncthreads();
        #pragma unroll 8
        for (int qq = 0; qq < 64; qq++) {
            float uval = sU[qq * 64 + r];
            ull uv = pack2(uval, uval);
            const ulonglong2* k2p = (const ulonglong2*)(sKT + qq * 64 + ig * 16);
            #pragma unroll
            for (int m2 = 0; m2 < 4; m2++) {
                ulonglong2 kk = k2p[m2];
                fma2ip(acc2[2 * m2 + 0], kk.x, uv);
                fma2ip(acc2[2 * m2 + 1], kk.y, uv);
            }
        }
    }
    #pragma unroll
    for (int m = 0; m < 8; m++) {
        float lo, hi; unpack2(acc2[m], lo, hi);
        int i = ig * 16 + 2 * m;
        g_buf[((size_t)c * NX + i) * R + r0 + r]     = lo;
        g_buf[((size_t)c * NX + i + 1) * R + r0 + r] = hi;
    }
}

// ---------------------------------------------------------------------------
// Kernel 2 (v3): boundary scan, unrolled x4 with STATIC prefetch regs and
// STATIC ping-pong buffers (no local-memory demotion, no runtime p-select).
// 128 CTAs x 128 threads (i = t>>1, r = t&1).
// ---------------------------------------------------------------------------
__global__ void k_phase2(const float* __restrict__ x0) {
    __shared__ __align__(16) float sxf[2][2][NX];  // [buf][r][i]
    const int t = threadIdx.x;  // 128
    const int r = t & 1;
    const int i = t >> 1;
    const int rg = blockIdx.x * 2 + r;

    ull a2[32];
    const ull* arow = (const ull*)(g_AL + i * NX);
    #pragma unroll
    for (int j2 = 0; j2 < 32; j2++) a2[j2] = arow[j2];

    float xi = x0[i * R + rg];
    sxf[0][r][i] = xi;
    __syncthreads();

    const size_t stride = (size_t)NX * R;
    float* gb = g_buf + (size_t)i * R + rg;

    float pf0 = gb[0 * stride];
    float pf1 = gb[1 * stride];
    float pf2 = gb[2 * stride];
    float pf3 = gb[3 * stride];

#define P2_STEP(CC, PF, RB, WB)                                               \
    {                                                                         \
        gb[(size_t)(CC) * stride] = xi;   /* Xstart[CC]; Pfin[CC] long read */\
        float pfnew = ((CC) + 4 < C_CHUNKS) ? gb[(size_t)((CC) + 4) * stride] \
                                            : 0.f;                            \
        const ull* xsrc = (const ull*)&sxf[RB][r][0];                         \
        ull A0 = 0ull, A1 = 0ull, A2 = 0ull, A3 = 0ull;                       \
        _Pragma("unroll")                                                     \
        for (int j2 = 0; j2 < 32; j2 += 4) {                                  \
            fma2ip(A0, a2[j2 + 0], xsrc[j2 + 0]);                             \
            fma2ip(A1, a2[j2 + 1], xsrc[j2 + 1]);                             \
            fma2ip(A2, a2[j2 + 2], xsrc[j2 + 2]);                             \
            fma2ip(A3, a2[j2 + 3], xsrc[j2 + 3]);                             \
        }                                                                     \
        float s0, s1, s2, s3, s4, s5, s6, s7;                                 \
        unpack2(A0, s0, s1); unpack2(A1, s2, s3);                             \
        unpack2(A2, s4, s5); unpack2(A3, s6, s7);                             \
        xi = (((s0 + s1) + (s2 + s3)) + ((s4 + s5) + (s6 + s7))) + (PF);      \
        (PF) = pfnew;                                                         \
        sxf[WB][r][i] = xi;                                                   \
        __syncthreads();                                                      \
    }

    #pragma unroll 1
    for (int c = 0; c < C_CHUNKS; c += 4) {
        P2_STEP(c + 0, pf0, 0, 1);
        P2_STEP(c + 1, pf1, 1, 0);
        P2_STEP(c + 2, pf2, 0, 1);
        P2_STEP(c + 3, pf3, 1, 0);
    }
#undef P2_STEP
}

// ---------------------------------------------------------------------------
// Kernel 3 (R7/R9 best, 317-319us): TWO columns per thread, packed f32x2
// in-place, x_k in smem scratch. 64 threads (2 warps), grid (C_CHUNKS, 2).
// ---------------------------------------------------------------------------
extern __shared__ __align__(16) char dsmem[];

__global__ void __launch_bounds__(64) k_phase3(
    const float* __restrict__ u, const float* __restrict__ A,
    const float* __restrict__ B, const float* __restrict__ Cy,
    const float* __restrict__ D,
    float* __restrict__ outY, float* __restrict__ outX)
{
    ull*   xs  = (ull*)dsmem;                          // [32][128] packed x pairs
    ull*   sA2 = (ull*)(dsmem + 32768);                // [j][i2] 64x32
    ull*   sB2 = (ull*)(dsmem + 32768 + 16384);        // [j][i2] 8x32
    ull*   sC2 = (ull*)(dsmem + 32768 + 16384 + 2048); // [o][j2] 8x32
    float* sD  = (float*)(dsmem + 32768 + 16384 + 4096);

    const int tid = threadIdx.x;                       // 64
    const int c = blockIdx.x;
    const int rA = blockIdx.y * 128 + tid;             // column a (col b = rA+64)

    for (int idx = tid; idx < 64 * 32; idx += 64) {
        int j = idx >> 5, i2 = idx & 31;
        sA2[idx] = pack2(A[(2 * i2) * NX + j], A[(2 * i2 + 1) * NX + j]);
    }
    for (int idx = tid; idx < NU * 32; idx += 64) {
        int j = idx >> 5, i2 = idx & 31;
        sB2[idx] = pack2(B[(2 * i2) * NU + j], B[(2 * i2 + 1) * NU + j]);
    }
    for (int idx = tid; idx < NY * 32; idx += 64) {
        int o = idx >> 5, j2 = idx & 31;
        sC2[idx] = pack2(Cy[o * NX + 2 * j2], Cy[o * NX + 2 * j2 + 1]);
    }
    if (tid < NY * NU) sD[tid] = D[tid];

    ull acc2a[32], acc2b[32];
    {
        const float* xsa = g_buf + (size_t)c * NX * R + rA;
        #pragma unroll
        for (int k = 0; k < 32; k++) {
            acc2a[k] = pack2(xsa[(2 * k) * R], xsa[(2 * k + 1) * R]);
            acc2b[k] = pack2(xsa[(2 * k) * R + 64], xsa[(2 * k + 1) * R + 64]);
        }
    }
    __syncthreads();

    const float* upa = u    + (size_t)c * L * NU * R + rA;
    float*       ypa = outY + (size_t)c * L * NY * R + rA;
    float*       xpa = outX + (size_t)c * L * NX * R + rA;

    #pragma unroll 1
    for (int step = 0; step < L; step++) {
        float ua[NU], ub[NU];
        #pragma unroll
        for (int j = 0; j < NU; j++) {
            ua[j] = upa[j * R];
            ub[j] = upa[j * R + 64];
        }

        #pragma unroll 2
        for (int o = 0; o < NY; o++) {
            ull ya = 0ull, yb = 0ull;
            const ulonglong2* c2 = (const ulonglong2*)(sC2 + o * 32);
            #pragma unroll
            for (int k2 = 0; k2 < 16; k2++) {
                ulonglong2 cc = c2[k2];
                fma2ip(ya, cc.x, acc2a[2 * k2 + 0]);
                fma2ip(ya, cc.y, acc2a[2 * k2 + 1]);
                fma2ip(yb, cc.x, acc2b[2 * k2 + 0]);
                fma2ip(yb, cc.y, acc2b[2 * k2 + 1]);
            }
            float la, ha; unpack2(ya, la, ha);
            float lb, hb; unpack2(yb, lb, hb);
            float dsa = 0.f, dsb = 0.f;
            #pragma unroll
            for (int j = 0; j < NU; j++) {
                float dv = sD[o * NU + j];
                dsa += dv * ua[j];
                dsb += dv * ub[j];
            }
            ypa[o * R]      = (la + ha) + dsa;
            ypa[o * R + 64] = (lb + hb) + dsb;
        }

        #pragma unroll
        for (int k = 0; k < 32; k++) {
            float la, ha; unpack2(acc2a[k], la, ha);
            float lb, hb; unpack2(acc2b[k], lb, hb);
            xpa[(2 * k) * R]          = la;
            xpa[(2 * k + 1) * R]      = ha;
            xpa[(2 * k) * R + 64]     = lb;
            xpa[(2 * k + 1) * R + 64] = hb;
            xs[k * 128 + tid]      = acc2a[k];
            xs[k * 128 + 64 + tid] = acc2b[k];
        }

        {
            #pragma unroll
            for (int k = 0; k < 32; k++) { acc2a[k] = 0ull; acc2b[k] = 0ull; }
            #pragma unroll 2
            for (int j = 0; j < NU; j++) {
                ull uaj = pack2(ua[j], ua[j]);
                ull ubj = pack2(ub[j], ub[j]);
                const ulonglong2* bj = (const ulonglong2*)(sB2 + j * 32);
                #pragma unroll
                for (int k2 = 0; k2 < 16; k2++) {
                    ulonglong2 bb = bj[k2];
                    fma2ip(acc2a[2 * k2 + 0], bb.x, uaj);
                    fma2ip(acc2a[2 * k2 + 1], bb.y, uaj);
                    fma2ip(acc2b[2 * k2 + 0], bb.x, ubj);
                    fma2ip(acc2b[2 * k2 + 1], bb.y, ubj);
                }
            }
        }

        #pragma unroll 2
        for (int j2 = 0; j2 < 32; j2++) {
            ull pa = xs[j2 * 128 + tid];
            ull pb = xs[j2 * 128 + 64 + tid];
            float xa0, xa1; unpack2(pa, xa0, xa1);
            float xb0, xb1; unpack2(pb, xb0, xb1);
            ull sa0 = pack2(xa0, xa0), sa1 = pack2(xa1, xa1);
            ull sb0 = pack2(xb0, xb0), sb1 = pack2(xb1, xb1);
            const ulonglong2* A0 = (const ulonglong2*)(sA2 + (2 * j2) * 32);
            const ulonglong2* A1 = (const ulonglong2*)(sA2 + (2 * j2 + 1) * 32);
            #pragma unroll
            for (int k2 = 0; k2 < 16; k2++) {
                ulonglong2 aa = A0[k2];
                fma2ip(acc2a[2 * k2 + 0], aa.x, sa0);
                fma2ip(acc2a[2 * k2 + 1], aa.y, sa0);
                fma2ip(acc2b[2 * k2 + 0], aa.x, sb0);
                fma2ip(acc2b[2 * k2 + 1], aa.y, sb0);
                ulonglong2 ab = A1[k2];
                fma2ip(acc2a[2 * k2 + 0], ab.x, sa1);
                fma2ip(acc2a[2 * k2 + 1], ab.y, sa1);
                fma2ip(acc2b[2 * k2 + 0], ab.x, sb1);
                fma2ip(acc2b[2 * k2 + 1], ab.y, sb1);
            }
        }

        upa += NU * R;
        ypa += NY * R;
        xpa += NX * R;
    }
}

#define SMEM_P3 (32768 + 16384 + 2048 + 2048 + 256)
#define SMEM_P0 ((4096 + 4096 + 8192) * 4)

// ---------------------------------------------------------------------------
extern "C" void kernel_launch(void* const* d_in, const int* in_sizes, int n_in,
                              void* d_out, int out_size) {
    const float* u  = (const float*)d_in[0];
    const float* x0 = (const float*)d_in[1];
    const float* A  = (const float*)d_in[2];
    const float* B  = (const float*)d_in[3];
    const float* Cy = (const float*)d_in[4];
    const float* D  = (const float*)d_in[5];
    float* outY = (float*)d_out;
    float* outX = (float*)d_out + (size_t)N_STEPS * NY * R;

    cudaFuncSetAttribute(k_phase3, cudaFuncAttributeMaxDynamicSharedMemorySize, SMEM_P3);
    cudaFuncSetAttribute(k_precompute, cudaFuncAttributeMaxDynamicSharedMemorySize, SMEM_P0);

    k_precompute<<<1, 512, SMEM_P0>>>(A, B);
    k_phase1<<<dim3(C_CHUNKS, R / 64), 256>>>(u);
    k_phase2<<<R / 2, 128>>>(x0);
    k_phase3<<<dim3(C_CHUNKS, 2), 64, SMEM_P3>>>(u, A, B, Cy, D, outY, outX);
}